// round 13
// baseline (speedup 1.0000x reference)
#include <cuda_runtime.h>

#define P      16384
#define P4     (P / 4)
#define BM     128
#define NC     10
#define KSEL   819
#define NMASK  9830
#define NT     512
#define EQCAP  512
#define CCAP   512

// scratch (no allocations allowed). INVARIANT: g_block is all-zero at entry of
// every kernel_launch execution (zeroed at module load; k_final re-zeroes each
// word right after consuming it).
__device__ unsigned char g_block[BM * P];

// monotone uint transform for float ordering (handles tiny negative d2)
__device__ __forceinline__ unsigned int fkey(float f) {
    unsigned int u = __float_as_uint(f);
    return u ^ ((u >> 31) ? 0xFFFFFFFFu : 0x80000000u);
}

// warp-aggregated histogram increment (pass 1 only: heavy bucket concentration)
__device__ __forceinline__ void hist_add_agg(int* hist, unsigned int bkt) {
    unsigned int m = __match_any_sync(0xFFFFFFFFu, bkt);
    int leader = __ffs(m) - 1;
    if ((int)(threadIdx.x & 31) == leader) atomicAdd(&hist[bkt], __popc(m));
}

// Warp-0 scan of the 256-bucket histogram; locates bucket holding rank
// `remaining`. Registers + shfl only: no block barriers inside.
__device__ __forceinline__ void find_bucket_warp(const int* hist, int remaining,
                                                 int* s_sb, int* s_cum) {
    int t = threadIdx.x;
    if (t < 32) {
        int v[8];
        int base = t * 8;
        #pragma unroll
        for (int j = 0; j < 8; j++) v[j] = hist[base + j];
        #pragma unroll
        for (int j = 1; j < 8; j++) v[j] += v[j - 1];
        int tot = v[7];
        int inc = tot;
        #pragma unroll
        for (int off = 1; off < 32; off <<= 1) {
            int n = __shfl_up_sync(0xFFFFFFFFu, inc, off);
            if (t >= off) inc += n;
        }
        int excl = inc - tot;
        if (excl < remaining && remaining <= inc) {
            int j = 7;
            #pragma unroll
            for (int jj = 6; jj >= 0; jj--)
                if (excl + v[jj] >= remaining) j = jj;
            *s_sb  = base + j;
            *s_cum = excl + (j ? v[j - 1] : 0);
        }
    }
}

// 4-pass radix rank-select over smem keys (byte-3 hist pre-built by caller).
__device__ unsigned int radix_select_from_hist(const unsigned int* keys, int r,
                                               int* hist, int* s_sb, int* s_cum,
                                               int* p_ties) {
    int t = threadIdx.x;
    __syncthreads();                       // fill-sweep hist atomics complete
    find_bucket_warp(hist, r, s_sb, s_cum);
    __syncthreads();
    unsigned int prefix = ((unsigned int)*s_sb) << 24;
    int remaining = r - *s_cum;
    const uint4* k4 = (const uint4*)keys;
    for (int shift = 16; shift >= 0; shift -= 8) {
        if (t < 256) hist[t] = 0;
        __syncthreads();
        int psh = shift + 8;
        for (int i = t; i < P4; i += NT) {
            uint4 kk = k4[i];
            unsigned int ks[4] = {kk.x, kk.y, kk.z, kk.w};
            #pragma unroll
            for (int j = 0; j < 4; j++) {
                unsigned int k = ks[j];
                if ((k >> psh) == (prefix >> psh))
                    atomicAdd(&hist[(k >> shift) & 255u], 1);
            }
        }
        __syncthreads();
        find_bucket_warp(hist, remaining, s_sb, s_cum);
        __syncthreads();
        prefix |= ((unsigned int)*s_sb) << shift;
        remaining -= *s_cum;
    }
    *p_ties = remaining;
    return prefix;
}

// Kernel 1 (was 2): one block per (row, center). Inline top-10 center select
// (identical across the row's 10 CTAs; CTA c takes rank-c candidate), then
// eager-JAX fp32 d2 + radix rank-819 select + mark block positions.
//   d2: norms un-fused (x*x+y*y)+z*z, dot = FMA chain, d2 = (ns+nc) - rn(2*dot)
__global__ void k_knn(const float* __restrict__ centers,
                      const float* __restrict__ rc) {
    extern __shared__ unsigned int s_keys[];   // P u32 (64KB)
    __shared__ int hist[256];
    __shared__ int s_sb, s_cum, s_eqcnt, s_cnt, s_ci;
    __shared__ int s_eq[EQCAP];
    __shared__ unsigned long long s_cand[CCAP];
    __shared__ unsigned long long s_min;
    int b = blockIdx.x / NC, c = blockIdx.x % NC;
    int t = threadIdx.x;

    // ---- inline center selection: rank-c of the 10 smallest rc[b,:] ----
    // uniforms in [0,1): raw uint order == float order; u64 (key<<32|idx)
    // gives stable-argsort tie semantics.
    {
        const uint4* row4 = (const uint4*)(rc + (size_t)b * P);
        unsigned int thresh = 0x3B800000u;       // 2^-8: E[count]=64
        unsigned int lo = 0, hi = 0x3F800000u;   // 1.0f
        int cnt = 0, iter = 0;
        bool degenerate = false;
        while (true) {
            if (t == 0) s_cnt = 0;
            __syncthreads();
            for (int i = t; i < P4; i += NT) {
                uint4 kk = row4[i];
                unsigned int ks[4] = {kk.x, kk.y, kk.z, kk.w};
                #pragma unroll
                for (int j = 0; j < 4; j++) {
                    if (ks[j] < thresh) {
                        int pos = atomicAdd(&s_cnt, 1);
                        if (pos < CCAP)
                            s_cand[pos] = ((unsigned long long)ks[j] << 32) | (unsigned int)(i * 4 + j);
                    }
                }
            }
            __syncthreads();
            cnt = s_cnt;
            if (cnt >= NC && cnt <= CCAP) break;
            if (cnt < NC) lo = thresh; else hi = thresh;
            if (hi - lo <= 1 || ++iter > 40) { degenerate = true; break; }
            thresh = lo + ((hi - lo) >> 1);
            __syncthreads();
        }
        if (!degenerate) {
            for (int i = t; i < cnt; i += NT) {
                unsigned long long me = s_cand[i];
                int rank = 0;
                for (int j = 0; j < cnt; j++) rank += (s_cand[j] < me);
                if (rank == c) s_ci = (int)(me & 0xFFFFFFFFull);
            }
        } else {
            // massive tie group straddles [NC, CCAP]: exact iterative c-th min
            unsigned long long low = 0;
            for (int i = 0; i <= c; i++) {
                if (t == 0) s_min = ~0ull;
                __syncthreads();
                unsigned long long local = ~0ull;
                for (int p = t; p < P; p += NT) {
                    unsigned long long key =
                        ((unsigned long long)__float_as_uint(rc[(size_t)b * P + p]) << 32) | (unsigned int)p;
                    if (key >= low && key < local) local = key;
                }
                atomicMin(&s_min, local);
                __syncthreads();
                if (t == 0 && i == c) s_ci = (int)(s_min & 0xFFFFFFFFull);
                low = s_min + 1;
                __syncthreads();
            }
        }
        __syncthreads();
    }
    int ci = s_ci;

    // ---- distances ----
    const float* cen = centers + (size_t)(b >> 1) * P * 3;
    float sx = cen[(size_t)ci * 3 + 0];
    float sy = cen[(size_t)ci * 3 + 1];
    float sz = cen[(size_t)ci * 3 + 2];
    float ns = __fadd_rn(__fadd_rn(__fmul_rn(sx, sx), __fmul_rn(sy, sy)), __fmul_rn(sz, sz));

    if (t < 256) hist[t] = 0;
    if (t == 0) s_eqcnt = 0;
    __syncthreads();

    const uint4* c4 = (const uint4*)cen;
    uint4* sk4 = (uint4*)s_keys;
    for (int g = t; g < P4; g += NT) {
        uint4 u0 = c4[g * 3 + 0];
        uint4 u1 = c4[g * 3 + 1];
        uint4 u2 = c4[g * 3 + 2];
        float xs[4] = {__uint_as_float(u0.x), __uint_as_float(u0.w),
                       __uint_as_float(u1.z), __uint_as_float(u2.y)};
        float ys[4] = {__uint_as_float(u0.y), __uint_as_float(u1.x),
                       __uint_as_float(u1.w), __uint_as_float(u2.z)};
        float zs[4] = {__uint_as_float(u0.z), __uint_as_float(u1.y),
                       __uint_as_float(u2.x), __uint_as_float(u2.w)};
        unsigned int kout[4];
        #pragma unroll
        for (int j = 0; j < 4; j++) {
            float x = xs[j], y = ys[j], z = zs[j];
            float nc2 = __fadd_rn(__fadd_rn(__fmul_rn(x, x), __fmul_rn(y, y)), __fmul_rn(z, z));
            float dot = __fmaf_rn(sz, z, __fmaf_rn(sy, y, __fmul_rn(sx, x)));
            float d2 = __fsub_rn(__fadd_rn(ns, nc2), __fmul_rn(2.0f, dot));
            kout[j] = fkey(d2);
        }
        sk4[g] = make_uint4(kout[0], kout[1], kout[2], kout[3]);
        #pragma unroll
        for (int j = 0; j < 4; j++) hist_add_agg(hist, kout[j] >> 24);
    }

    int ties;
    unsigned int T = radix_select_from_hist(s_keys, KSEL, hist, &s_sb, &s_cum, &ties);

    unsigned char* brow = g_block + (size_t)b * P;
    const uint4* sk4c = (const uint4*)s_keys;
    for (int i = t; i < P4; i += NT) {
        uint4 kk = sk4c[i];
        unsigned int ks[4] = {kk.x, kk.y, kk.z, kk.w};
        int p0 = i * 4;
        #pragma unroll
        for (int j = 0; j < 4; j++) {
            unsigned int k = ks[j];
            if (k < T) brow[p0 + j] = 1;
            else if (k == T) {
                int pos = atomicAdd(&s_eqcnt, 1);
                if (pos < EQCAP) s_eq[pos] = p0 + j;
            }
        }
    }
    __syncthreads();
    int L = s_eqcnt;
    if (L <= EQCAP) {
        for (int i = t; i < L; i += NT) {
            int p = s_eq[i]; int rank = 0;
            for (int j = 0; j < L; j++) if (s_eq[j] < p) rank++;
            if (rank < ties) brow[p] = 1;
        }
    } else {
        for (int p = t; p < P; p += NT) {
            if (s_keys[p] == T) {
                int rank = 0;
                for (int j = 0; j < p; j++) if (s_keys[j] == T) rank++;
                if (rank < ties) brow[p] = 1;
            }
        }
    }
}

// Kernel 2: per row, select (9830 - n_block) smallest rand_mask among
// non-block positions; write float32 mask (0.0/1.0). Re-zeroes g_block
// (each word immediately after consumption) to maintain the entry invariant.
__global__ void k_final(const float* __restrict__ rm, float* __restrict__ out) {
    extern __shared__ unsigned int s_keys[];   // P u32 (64KB)
    __shared__ int hist[256];
    __shared__ int s_sb, s_cum, s_eqcnt, s_nblk;
    __shared__ int s_eq[EQCAP];
    int b = blockIdx.x, t = threadIdx.x;

    if (t < 256) hist[t] = 0;
    if (t == 0) { s_eqcnt = 0; s_nblk = 0; }
    __syncthreads();

    unsigned int* b4 = (unsigned int*)(g_block + (size_t)b * P);
    const uint4* r4 = (const uint4*)(rm + (size_t)b * P);
    uint4* sk4 = (uint4*)s_keys;
    int local = 0;
    for (int i = t; i < P4; i += NT) {
        unsigned int blk4 = b4[i];     // 4 packed 0/1 bytes
        b4[i] = 0;                     // re-zero for next run (same thread/word)
        uint4 rr = r4[i];              // uniforms in [0,1): raw order OK
        local += __popc(blk4);
        uint4 kk;
        kk.x = (blk4 & 0x000000FFu) ? 0xFFFFFFFFu : rr.x;
        kk.y = (blk4 & 0x0000FF00u) ? 0xFFFFFFFFu : rr.y;
        kk.z = (blk4 & 0x00FF0000u) ? 0xFFFFFFFFu : rr.z;
        kk.w = (blk4 & 0xFF000000u) ? 0xFFFFFFFFu : rr.w;
        sk4[i] = kk;
        hist_add_agg(hist, kk.x >> 24);
        hist_add_agg(hist, kk.y >> 24);
        hist_add_agg(hist, kk.z >> 24);
        hist_add_agg(hist, kk.w >> 24);
    }
    for (int off = 16; off; off >>= 1) local += __shfl_down_sync(0xFFFFFFFFu, local, off);
    if ((t & 31) == 0) atomicAdd(&s_nblk, local);
    __syncthreads();
    int rank = NMASK - s_nblk;   // >= 1640 (n_block <= 8190)

    int ties;
    unsigned int T = radix_select_from_hist(s_keys, rank, hist, &s_sb, &s_cum, &ties);

    float* orow = out + (size_t)b * P;
    float4* o4 = (float4*)orow;
    const uint4* sk4c = (const uint4*)s_keys;
    for (int i = t; i < P4; i += NT) {
        uint4 kk = sk4c[i];
        unsigned int ks[4] = {kk.x, kk.y, kk.z, kk.w};
        float v[4];
        int p0 = i * 4;
        #pragma unroll
        for (int j = 0; j < 4; j++) {
            unsigned int k = ks[j];
            v[j] = (k == 0xFFFFFFFFu || k < T) ? 1.0f : 0.0f;
            if (k == T) {
                int pos = atomicAdd(&s_eqcnt, 1);
                if (pos < EQCAP) s_eq[pos] = p0 + j;
            }
        }
        o4[i] = make_float4(v[0], v[1], v[2], v[3]);
    }
    __syncthreads();
    int L = s_eqcnt;
    if (L <= EQCAP) {
        for (int i = t; i < L; i += NT) {
            int p = s_eq[i]; int rank2 = 0;
            for (int j = 0; j < L; j++) if (s_eq[j] < p) rank2++;
            if (rank2 < ties) orow[p] = 1.0f;
        }
    } else {
        for (int p = t; p < P; p += NT) {
            if (s_keys[p] == T) {
                int rank2 = 0;
                for (int j = 0; j < p; j++) if (s_keys[j] == T) rank2++;
                if (rank2 < ties) orow[p] = 1.0f;
            }
        }
    }
}

extern "C" void kernel_launch(void* const* d_in, const int* in_sizes, int n_in,
                              void* d_out, int out_size) {
    const float* centers = (const float*)d_in[0];  // [64, 16384, 3]
    const float* rc      = (const float*)d_in[1];  // [128, 16384]
    const float* rm      = (const float*)d_in[2];  // [128, 16384]
    float* out           = (float*)d_out;          // [128, 16384] float32 (bool->f32)

    const int SMEM = P * 4;   // 64KB keys
    cudaFuncSetAttribute(k_knn,   cudaFuncAttributeMaxDynamicSharedMemorySize, SMEM);
    cudaFuncSetAttribute(k_final, cudaFuncAttributeMaxDynamicSharedMemorySize, SMEM);

    k_knn<<<BM * NC, NT, SMEM>>>(centers, rc);
    k_final<<<BM, NT, SMEM>>>(rm, out);
}

// round 16
// speedup vs baseline: 1.1830x; 1.1830x over previous
#include <cuda_runtime.h>

#define P      16384
#define P4     (P / 4)
#define BM     128
#define NC     10
#define KSEL   819
#define NMASK  9830
#define EQCAP  512
#define CCAP   1024

// scratch (no allocations allowed)
__device__ unsigned char g_block[BM * P];
__device__ int g_cidx[BM * NC];

// monotone uint transform for float ordering (handles tiny negative d2)
__device__ __forceinline__ unsigned int fkey(float f) {
    unsigned int u = __float_as_uint(f);
    return u ^ ((u >> 31) ? 0xFFFFFFFFu : 0x80000000u);
}

// warp-aggregated histogram increment (pass 1 only: heavy bucket concentration)
__device__ __forceinline__ void hist_add_agg(int* hist, unsigned int bkt) {
    unsigned int m = __match_any_sync(0xFFFFFFFFu, bkt);
    int leader = __ffs(m) - 1;
    if ((int)(threadIdx.x & 31) == leader) atomicAdd(&hist[bkt], __popc(m));
}

// Warp-0 scan of the 256-bucket histogram; locates bucket holding rank
// `remaining`. Registers + shfl only: no block barriers inside.
__device__ __forceinline__ void find_bucket_warp(const int* hist, int remaining,
                                                 int* s_sb, int* s_cum) {
    int t = threadIdx.x;
    if (t < 32) {
        int v[8];
        int base = t * 8;
        #pragma unroll
        for (int j = 0; j < 8; j++) v[j] = hist[base + j];
        #pragma unroll
        for (int j = 1; j < 8; j++) v[j] += v[j - 1];
        int tot = v[7];
        int inc = tot;
        #pragma unroll
        for (int off = 1; off < 32; off <<= 1) {
            int n = __shfl_up_sync(0xFFFFFFFFu, inc, off);
            if (t >= off) inc += n;
        }
        int excl = inc - tot;
        if (excl < remaining && remaining <= inc) {
            int j = 7;
            #pragma unroll
            for (int jj = 6; jj >= 0; jj--)
                if (excl + v[jj] >= remaining) j = jj;
            *s_sb  = base + j;
            *s_cum = excl + (j ? v[j - 1] : 0);
        }
    }
}

// 4-pass radix rank-select over smem keys (byte-3 hist pre-built by caller).
template <int NTH>
__device__ unsigned int radix_select_from_hist(const unsigned int* keys, int r,
                                               int* hist, int* s_sb, int* s_cum,
                                               int* p_ties) {
    int t = threadIdx.x;
    __syncthreads();                       // fill-sweep hist atomics complete
    find_bucket_warp(hist, r, s_sb, s_cum);
    __syncthreads();
    unsigned int prefix = ((unsigned int)*s_sb) << 24;
    int remaining = r - *s_cum;
    const uint4* k4 = (const uint4*)keys;
    for (int shift = 16; shift >= 0; shift -= 8) {
        if (t < 256) hist[t] = 0;
        __syncthreads();
        int psh = shift + 8;
        for (int i = t; i < P4; i += NTH) {
            uint4 kk = k4[i];
            unsigned int ks[4] = {kk.x, kk.y, kk.z, kk.w};
            #pragma unroll
            for (int j = 0; j < 4; j++) {
                unsigned int k = ks[j];
                if ((k >> psh) == (prefix >> psh))
                    atomicAdd(&hist[(k >> shift) & 255u], 1);
            }
        }
        __syncthreads();
        find_bucket_warp(hist, remaining, s_sb, s_cum);
        __syncthreads();
        prefix |= ((unsigned int)*s_sb) << shift;
        remaining -= *s_cum;
    }
    *p_ties = remaining;
    return prefix;
}

// Kernel 1: zero block scratch; select the 10 smallest rand_centers by
// threshold-filter (+ uint-bisection + exact-tie fallback). NT=1024 (single
// wave, latency-bound -> max warps). Set semantics (union downstream).
__global__ void __launch_bounds__(1024) k_centers(const float* __restrict__ rc) {
    const int NTH = 1024;
    __shared__ unsigned long long s_cand[CCAP];
    __shared__ int s_cnt, s_nsel;
    __shared__ unsigned long long s_min;
    int b = blockIdx.x, t = threadIdx.x;

    int4 z4 = make_int4(0, 0, 0, 0);
    int4* brow4 = (int4*)(g_block + (size_t)b * P);
    for (int i = t; i < P / 16; i += NTH) brow4[i] = z4;

    const uint4* row4 = (const uint4*)(rc + (size_t)b * P);
    unsigned int thresh = 0x3B800000u;           // 2^-8: E[count]=64
    unsigned int lo = 0, hi = 0x3F800000u;       // 1.0f
    int cnt = 0, iter = 0;
    bool degenerate = false;
    while (true) {
        if (t == 0) s_cnt = 0;
        __syncthreads();
        for (int i = t; i < P4; i += NTH) {
            uint4 kk = row4[i];
            unsigned int ks[4] = {kk.x, kk.y, kk.z, kk.w};
            #pragma unroll
            for (int j = 0; j < 4; j++) {
                if (ks[j] < thresh) {
                    int pos = atomicAdd(&s_cnt, 1);
                    if (pos < CCAP)
                        s_cand[pos] = ((unsigned long long)ks[j] << 32) | (unsigned int)(i * 4 + j);
                }
            }
        }
        __syncthreads();
        cnt = s_cnt;
        if (cnt >= NC && cnt <= CCAP) break;
        if (cnt < NC) lo = thresh; else hi = thresh;
        if (hi - lo <= 1 || ++iter > 40) { degenerate = true; break; }
        thresh = lo + ((hi - lo) >> 1);
        __syncthreads();
    }

    int* cidx = g_cidx + b * NC;
    if (!degenerate) {
        if (t == 0) s_nsel = 0;
        __syncthreads();
        for (int i = t; i < cnt; i += NTH) {
            unsigned long long me = s_cand[i];
            int rank = 0;
            for (int j = 0; j < cnt; j++) rank += (s_cand[j] < me);
            if (rank < NC) { int pos = atomicAdd(&s_nsel, 1); cidx[pos] = (int)(me & 0xFFFFFFFFull); }
        }
    } else {
        unsigned long long low = 0;
        for (int i = 0; i < NC; i++) {
            if (t == 0) s_min = ~0ull;
            __syncthreads();
            unsigned long long local = ~0ull;
            for (int p = t; p < P; p += NTH) {
                unsigned long long key =
                    ((unsigned long long)__float_as_uint(rc[(size_t)b * P + p]) << 32) | (unsigned int)p;
                if (key >= low && key < local) local = key;
            }
            atomicMin(&s_min, local);
            __syncthreads();
            if (t == 0) cidx[i] = (int)(s_min & 0xFFFFFFFFull);
            low = s_min + 1;
            __syncthreads();
        }
    }
}

// Kernel 2: one block per (row, center). Eager-JAX fp32 d2:
//   norms un-fused (x*x+y*y)+z*z, dot = FMA chain, d2 = (ns+nc) - rn(2*dot).
// NT=512: 3 CTAs/SM x 16 warps = 48 resident warps (latency already hidden).
__global__ void __launch_bounds__(512) k_knn(const float* __restrict__ centers) {
    const int NTH = 512;
    extern __shared__ unsigned int s_keys[];   // P u32 (64KB)
    __shared__ int hist[256];
    __shared__ int s_sb, s_cum, s_eqcnt;
    __shared__ int s_eq[EQCAP];
    int b = blockIdx.x / NC, c = blockIdx.x % NC;
    int t = threadIdx.x;

    const float* cen = centers + (size_t)(b >> 1) * P * 3;
    int ci = g_cidx[b * NC + c];
    float sx = cen[(size_t)ci * 3 + 0];
    float sy = cen[(size_t)ci * 3 + 1];
    float sz = cen[(size_t)ci * 3 + 2];
    float ns = __fadd_rn(__fadd_rn(__fmul_rn(sx, sx), __fmul_rn(sy, sy)), __fmul_rn(sz, sz));

    if (t < 256) hist[t] = 0;
    if (t == 0) s_eqcnt = 0;
    __syncthreads();

    const uint4* c4 = (const uint4*)cen;
    uint4* sk4 = (uint4*)s_keys;
    for (int g = t; g < P4; g += NTH) {
        uint4 u0 = c4[g * 3 + 0];
        uint4 u1 = c4[g * 3 + 1];
        uint4 u2 = c4[g * 3 + 2];
        float xs[4] = {__uint_as_float(u0.x), __uint_as_float(u0.w),
                       __uint_as_float(u1.z), __uint_as_float(u2.y)};
        float ys[4] = {__uint_as_float(u0.y), __uint_as_float(u1.x),
                       __uint_as_float(u1.w), __uint_as_float(u2.z)};
        float zs[4] = {__uint_as_float(u0.z), __uint_as_float(u1.y),
                       __uint_as_float(u2.x), __uint_as_float(u2.w)};
        unsigned int kout[4];
        #pragma unroll
        for (int j = 0; j < 4; j++) {
            float x = xs[j], y = ys[j], z = zs[j];
            float nc2 = __fadd_rn(__fadd_rn(__fmul_rn(x, x), __fmul_rn(y, y)), __fmul_rn(z, z));
            float dot = __fmaf_rn(sz, z, __fmaf_rn(sy, y, __fmul_rn(sx, x)));
            float d2 = __fsub_rn(__fadd_rn(ns, nc2), __fmul_rn(2.0f, dot));
            kout[j] = fkey(d2);
        }
        sk4[g] = make_uint4(kout[0], kout[1], kout[2], kout[3]);
        #pragma unroll
        for (int j = 0; j < 4; j++) hist_add_agg(hist, kout[j] >> 24);
    }

    int ties;
    unsigned int T = radix_select_from_hist<NTH>(s_keys, KSEL, hist, &s_sb, &s_cum, &ties);

    unsigned char* brow = g_block + (size_t)b * P;
    const uint4* sk4c = (const uint4*)s_keys;
    for (int i = t; i < P4; i += NTH) {
        uint4 kk = sk4c[i];
        unsigned int ks[4] = {kk.x, kk.y, kk.z, kk.w};
        int p0 = i * 4;
        #pragma unroll
        for (int j = 0; j < 4; j++) {
            unsigned int k = ks[j];
            if (k < T) brow[p0 + j] = 1;
            else if (k == T) {
                int pos = atomicAdd(&s_eqcnt, 1);
                if (pos < EQCAP) s_eq[pos] = p0 + j;
            }
        }
    }
    __syncthreads();
    int L = s_eqcnt;
    if (L <= EQCAP) {
        for (int i = t; i < L; i += NTH) {
            int p = s_eq[i]; int rank = 0;
            for (int j = 0; j < L; j++) if (s_eq[j] < p) rank++;
            if (rank < ties) brow[p] = 1;
        }
    } else {
        for (int p = t; p < P; p += NTH) {
            if (s_keys[p] == T) {
                int rank = 0;
                for (int j = 0; j < p; j++) if (s_keys[j] == T) rank++;
                if (rank < ties) brow[p] = 1;
            }
        }
    }
}

// Kernel 3: per row, select (9830 - n_block) smallest rand_mask among
// non-block positions; write float32 mask (0.0/1.0). NT=1024 (single wave,
// latency-bound -> max warps).
__global__ void __launch_bounds__(1024) k_final(const float* __restrict__ rm,
                                                float* __restrict__ out) {
    const int NTH = 1024;
    extern __shared__ unsigned int s_keys[];   // P u32 (64KB)
    __shared__ int hist[256];
    __shared__ int s_sb, s_cum, s_eqcnt, s_nblk;
    __shared__ int s_eq[EQCAP];
    int b = blockIdx.x, t = threadIdx.x;

    if (t < 256) hist[t] = 0;
    if (t == 0) { s_eqcnt = 0; s_nblk = 0; }
    __syncthreads();

    const unsigned int* b4 = (const unsigned int*)(g_block + (size_t)b * P);
    const uint4* r4 = (const uint4*)(rm + (size_t)b * P);
    uint4* sk4 = (uint4*)s_keys;
    int local = 0;
    for (int i = t; i < P4; i += NTH) {
        unsigned int blk4 = b4[i];     // 4 packed 0/1 bytes
        uint4 rr = r4[i];              // uniforms in [0,1): raw order OK
        local += __popc(blk4);
        uint4 kk;
        kk.x = (blk4 & 0x000000FFu) ? 0xFFFFFFFFu : rr.x;
        kk.y = (blk4 & 0x0000FF00u) ? 0xFFFFFFFFu : rr.y;
        kk.z = (blk4 & 0x00FF0000u) ? 0xFFFFFFFFu : rr.z;
        kk.w = (blk4 & 0xFF000000u) ? 0xFFFFFFFFu : rr.w;
        sk4[i] = kk;
        hist_add_agg(hist, kk.x >> 24);
        hist_add_agg(hist, kk.y >> 24);
        hist_add_agg(hist, kk.z >> 24);
        hist_add_agg(hist, kk.w >> 24);
    }
    for (int off = 16; off; off >>= 1) local += __shfl_down_sync(0xFFFFFFFFu, local, off);
    if ((t & 31) == 0) atomicAdd(&s_nblk, local);
    __syncthreads();
    int rank = NMASK - s_nblk;   // >= 1640 (n_block <= 8190)

    int ties;
    unsigned int T = radix_select_from_hist<NTH>(s_keys, rank, hist, &s_sb, &s_cum, &ties);

    float* orow = out + (size_t)b * P;
    float4* o4 = (float4*)orow;
    const uint4* sk4c = (const uint4*)s_keys;
    for (int i = t; i < P4; i += NTH) {
        uint4 kk = sk4c[i];
        unsigned int ks[4] = {kk.x, kk.y, kk.z, kk.w};
        float v[4];
        int p0 = i * 4;
        #pragma unroll
        for (int j = 0; j < 4; j++) {
            unsigned int k = ks[j];
            v[j] = (k == 0xFFFFFFFFu || k < T) ? 1.0f : 0.0f;
            if (k == T) {
                int pos = atomicAdd(&s_eqcnt, 1);
                if (pos < EQCAP) s_eq[pos] = p0 + j;
            }
        }
        o4[i] = make_float4(v[0], v[1], v[2], v[3]);
    }
    __syncthreads();
    int L = s_eqcnt;
    if (L <= EQCAP) {
        for (int i = t; i < L; i += NTH) {
            int p = s_eq[i]; int rank2 = 0;
            for (int j = 0; j < L; j++) if (s_eq[j] < p) rank2++;
            if (rank2 < ties) orow[p] = 1.0f;
        }
    } else {
        for (int p = t; p < P; p += NTH) {
            if (s_keys[p] == T) {
                int rank2 = 0;
                for (int j = 0; j < p; j++) if (s_keys[j] == T) rank2++;
                if (rank2 < ties) orow[p] = 1.0f;
            }
        }
    }
}

extern "C" void kernel_launch(void* const* d_in, const int* in_sizes, int n_in,
                              void* d_out, int out_size) {
    const float* centers = (const float*)d_in[0];  // [64, 16384, 3]
    const float* rc      = (const float*)d_in[1];  // [128, 16384]
    const float* rm      = (const float*)d_in[2];  // [128, 16384]
    float* out           = (float*)d_out;          // [128, 16384] float32 (bool->f32)

    const int SMEM = P * 4;   // 64KB keys
    cudaFuncSetAttribute(k_knn,   cudaFuncAttributeMaxDynamicSharedMemorySize, SMEM);
    cudaFuncSetAttribute(k_final, cudaFuncAttributeMaxDynamicSharedMemorySize, SMEM);

    k_centers<<<BM, 1024>>>(rc);
    k_knn<<<BM * NC, 512, SMEM>>>(centers);
    k_final<<<BM, 1024, SMEM>>>(rm, out);
}